// round 2
// baseline (speedup 1.0000x reference)
#include <cuda_runtime.h>
#include <stdint.h>
#include <math.h>

#define N_NODES 50000
#define N_EDGES 200000
#define D_IN    128
#define DD      256
#define N_LAYERS 4
#define N_RELS  4
#define NUM_M   1024
#define NUM_R   64
#define N_ALL   (NUM_R + NUM_M)
#define GW      1280

__device__ float g_featsA[N_NODES * DD];
__device__ float g_featsB[N_NODES * DD];
__device__ float g_G[(size_t)N_NODES * GW];
__device__ float g_Wcat[N_LAYERS * 256 * GW];
__device__ int   g_cnt[N_RELS * N_NODES];
__device__ int   g_deg[N_NODES];
__device__ int   g_off[N_NODES + 1];
__device__ int   g_cursor[N_NODES];
__device__ int   g_esort[N_EDGES];
__device__ int   g_start[NUM_M + 1];
__device__ float g_Hall[N_ALL * DD];
__device__ float g_pu[N_ALL * 512];
__device__ float g_qz[N_ALL * 512];
__device__ float g_u[N_ALL * DD];
__device__ float g_zM[NUM_M * DD];
__device__ float g_zR[NUM_R * DD];
__device__ float g_An[NUM_M * NUM_R];
__device__ float g_pzm[NUM_M * DD];
__device__ float g_pzl[NUM_M * DD];
__device__ float g_repM[NUM_M * 512];
__device__ float g_repR[NUM_R * 512];
__device__ float g_hidM[NUM_M * 256];
__device__ float g_hidR[NUM_R * 256];
__device__ float g_acc[4];

__host__ __device__ __forceinline__ uint32_t rotl32(uint32_t x, int d) {
    return (x << d) | (x >> (32 - d));
}
__host__ __device__ __forceinline__ void tf2x32(uint32_t k0, uint32_t k1,
                                                uint32_t x0, uint32_t x1,
                                                uint32_t& o0, uint32_t& o1) {
    uint32_t ks2 = k0 ^ k1 ^ 0x1BD11BDAu;
    x0 += k0; x1 += k1;
#define TF_RND(R) { x0 += x1; x1 = rotl32(x1, R); x1 ^= x0; }
    TF_RND(13) TF_RND(15) TF_RND(26) TF_RND(6)
    x0 += k1;  x1 += ks2 + 1u;
    TF_RND(17) TF_RND(29) TF_RND(16) TF_RND(24)
    x0 += ks2; x1 += k0 + 2u;
    TF_RND(13) TF_RND(15) TF_RND(26) TF_RND(6)
    x0 += k0;  x1 += k1 + 3u;
    TF_RND(17) TF_RND(29) TF_RND(16) TF_RND(24)
    x0 += k1;  x1 += ks2 + 4u;
    TF_RND(13) TF_RND(15) TF_RND(26) TF_RND(6)
    x0 += ks2; x1 += k0 + 5u;
#undef TF_RND
    o0 = x0; o1 = x1;
}
// partitionable-mode random_bits: element i -> b1^b2 of tf(key, 0, i)
__device__ __forceinline__ uint32_t rbits(uint32_t k0, uint32_t k1, uint32_t i) {
    uint32_t o0, o1; tf2x32(k0, k1, 0u, i, o0, o1); return o0 ^ o1;
}
__device__ __forceinline__ float erfinv_xla(float x) {
    float w = -log1pf(-x * x), p;
    if (w < 5.0f) {
        w -= 2.5f;
        p = 2.81022636e-08f;
        p = fmaf(p, w, 3.43273939e-07f);  p = fmaf(p, w, -3.5233877e-06f);
        p = fmaf(p, w, -4.39150654e-06f); p = fmaf(p, w, 0.00021858087f);
        p = fmaf(p, w, -0.00125372503f);  p = fmaf(p, w, -0.00417768164f);
        p = fmaf(p, w, 0.246640727f);     p = fmaf(p, w, 1.50140941f);
    } else {
        w = sqrtf(w) - 3.0f;
        p = -0.000200214257f;
        p = fmaf(p, w, 0.000100950558f);  p = fmaf(p, w, 0.00134934322f);
        p = fmaf(p, w, -0.00367342844f);  p = fmaf(p, w, 0.00573950773f);
        p = fmaf(p, w, -0.0076224613f);   p = fmaf(p, w, 0.00943887047f);
        p = fmaf(p, w, 1.00167406f);      p = fmaf(p, w, 2.83297682f);
    }
    return p * x;
}
__device__ __forceinline__ float u01(uint32_t b) {
    return __uint_as_float((b >> 9) | 0x3f800000u) - 1.0f;
}
__device__ __forceinline__ float nrm(uint32_t b) {
    const float LO = -0.99999994f;
    float v = u01(b) * 2.0f + LO;
    v = fmaxf(LO, v);
    return 1.41421356f * erfinv_xla(v);
}
__device__ __forceinline__ float unif(uint32_t b) {
    const float MN = 1e-06f;
    float v = u01(b) * (0.999999f - MN) + MN;
    return fmaxf(MN, v);
}

__global__ void k_zero_init() {
    int i = blockIdx.x * blockDim.x + threadIdx.x;
    if (i < N_RELS * N_NODES) g_cnt[i] = 0;
    if (i < N_NODES) g_deg[i] = 0;
    if (i < 4) g_acc[i] = 0.0f;
}
__global__ void k_count(const int* __restrict__ ei, const int* __restrict__ et) {
    int e = blockIdx.x * blockDim.x + threadIdx.x;
    if (e >= N_EDGES) return;
    int d = ei[N_EDGES + e];
    atomicAdd(&g_cnt[et[e] * N_NODES + d], 1);
    atomicAdd(&g_deg[d], 1);
}
__global__ void k_scan() {
    __shared__ int part[1024];
    int tid = threadIdx.x;
    const int chunk = (N_NODES + 1023) / 1024;
    int lo = tid * chunk, hi = min(lo + chunk, N_NODES);
    int s = 0;
    for (int i = lo; i < hi; i++) s += g_deg[i];
    part[tid] = s;
    __syncthreads();
    for (int o = 1; o < 1024; o <<= 1) {
        int v = (tid >= o) ? part[tid - o] : 0;
        __syncthreads(); part[tid] += v; __syncthreads();
    }
    int run = part[tid] - s;
    for (int i = lo; i < hi; i++) { g_off[i] = run; run += g_deg[i]; }
    if (tid == 1023) g_off[N_NODES] = run;
}
__global__ void k_cursor() {
    int i = blockIdx.x * blockDim.x + threadIdx.x;
    if (i < N_NODES) g_cursor[i] = g_off[i];
}
__global__ void k_scatter(const int* __restrict__ ei) {
    int e = blockIdx.x * blockDim.x + threadIdx.x;
    if (e >= N_EDGES) return;
    int p = atomicAdd(&g_cursor[ei[N_EDGES + e]], 1);
    g_esort[p] = e;
}
__global__ void k_wcat(const float* __restrict__ Wroot, const float* __restrict__ Wr) {
    int idx = blockIdx.x * blockDim.x + threadIdx.x;
    if (idx >= N_LAYERS * 256 * GW) return;
    int l = idx / (256 * GW), rem = idx % (256 * GW);
    int k = rem / GW, j = rem % GW;
    float v;
    if (j < 256) v = Wroot[((size_t)l * 256 + k) * 256 + j];
    else {
        int r = (j >> 8) - 1, h = j & 255;
        v = Wr[(((size_t)l * 4 + r) * 256 + k) * 256 + h];
    }
    g_Wcat[idx] = v;
}

__global__ void __launch_bounds__(256)
k_sgemm(const float* __restrict__ A, const float* __restrict__ B,
        const float* __restrict__ bias, float* __restrict__ C,
        int M, int N, int K, int relu_in, int relu_out) {
    __shared__ float As[8][128];
    __shared__ float Bs[8][128];
    int bm = blockIdx.y * 128, bn = blockIdx.x * 128;
    int tid = threadIdx.x, tr = tid >> 4, tc = tid & 15;
    float acc[8][8];
#pragma unroll
    for (int i = 0; i < 8; i++)
#pragma unroll
        for (int j = 0; j < 8; j++) acc[i][j] = 0.f;
    int aRow = tid >> 1, aCol = (tid & 1) * 4;
    int bRow = tid >> 5, bCol = (tid & 31) * 4;
    for (int k0 = 0; k0 < K; k0 += 8) {
        float4 av = make_float4(0.f, 0.f, 0.f, 0.f);
        if (bm + aRow < M)
            av = *(const float4*)(A + (size_t)(bm + aRow) * K + k0 + aCol);
        if (relu_in) {
            av.x = fmaxf(av.x, 0.f); av.y = fmaxf(av.y, 0.f);
            av.z = fmaxf(av.z, 0.f); av.w = fmaxf(av.w, 0.f);
        }
        As[aCol + 0][aRow] = av.x; As[aCol + 1][aRow] = av.y;
        As[aCol + 2][aRow] = av.z; As[aCol + 3][aRow] = av.w;
        float4 bv = make_float4(0.f, 0.f, 0.f, 0.f);
        if (bn + bCol < N)
            bv = *(const float4*)(B + (size_t)(k0 + bRow) * N + bn + bCol);
        *(float4*)&Bs[bRow][bCol] = bv;
        __syncthreads();
#pragma unroll
        for (int kk = 0; kk < 8; kk++) {
            float a[8], b[8];
            *(float4*)(a)     = *(const float4*)&As[kk][tr * 8];
            *(float4*)(a + 4) = *(const float4*)&As[kk][tr * 8 + 4];
            *(float4*)(b)     = *(const float4*)&Bs[kk][tc * 8];
            *(float4*)(b + 4) = *(const float4*)&Bs[kk][tc * 8 + 4];
#pragma unroll
            for (int i = 0; i < 8; i++)
#pragma unroll
                for (int j = 0; j < 8; j++) acc[i][j] = fmaf(a[i], b[j], acc[i][j]);
        }
        __syncthreads();
    }
#pragma unroll
    for (int i = 0; i < 8; i++) {
        int row = bm + tr * 8 + i;
        if (row >= M) continue;
#pragma unroll
        for (int j = 0; j < 8; j++) {
            int col = bn + tc * 8 + j;
            if (col >= N) continue;
            float v = acc[i][j];
            if (bias) v += bias[col];
            if (relu_out) v = fmaxf(v, 0.f);
            C[(size_t)row * N + col] = v;
        }
    }
}

__global__ void k_agg(const int* __restrict__ ei, const int* __restrict__ et,
                      const float* __restrict__ bias, float* __restrict__ out, int relu) {
    int d = (blockIdx.x * blockDim.x + threadIdx.x) >> 5;
    int lane = threadIdx.x & 31;
    if (d >= N_NODES) return;
    float acc[8];
    const float* g0 = g_G + (size_t)d * GW;
#pragma unroll
    for (int j = 0; j < 8; j++) acc[j] = g0[lane + 32 * j] + bias[lane + 32 * j];
    int s = g_off[d], e = g_off[d + 1];
    for (int i = s; i < e; i++) {
        int eid = g_esort[i];
        int sn = ei[eid], r = et[eid];
        float inv = 1.0f / (float)g_cnt[r * N_NODES + d];
        const float* gp = g_G + (size_t)sn * GW + 256 + (r << 8);
#pragma unroll
        for (int j = 0; j < 8; j++) acc[j] = fmaf(gp[lane + 32 * j], inv, acc[j]);
    }
#pragma unroll
    for (int j = 0; j < 8; j++) {
        float v = acc[j];
        if (relu) v = fmaxf(v, 0.f);
        out[(size_t)d * DD + lane + 32 * j] = v;
    }
}

__global__ void k_starts(const int* __restrict__ batch) {
    int m = blockIdx.x * blockDim.x + threadIdx.x;
    if (m > NUM_M) return;
    int lo = 0, hi = N_NODES;
    while (lo < hi) { int mid = (lo + hi) >> 1; if (batch[mid] < m) lo = mid + 1; else hi = mid; }
    g_start[m] = lo;
}
__global__ void k_copyHR(const float* __restrict__ HR) {
    int i = blockIdx.x * blockDim.x + threadIdx.x;
    if (i < NUM_R * DD) g_Hall[i] = HR[i];
}
__global__ void k_gmean(const float* __restrict__ feats) {
    int m = blockIdx.x, c = threadIdx.x;
    int s = g_start[m], e = g_start[m + 1];
    float acc = 0.f;
    for (int n = s; n < e; n++) acc += feats[(size_t)n * DD + c];
    g_Hall[(size_t)(NUM_R + m) * DD + c] = acc / fmaxf((float)(e - s), 1.0f);
}

__global__ void k_sample_u(unsigned k0, unsigned k1) {
    int i = blockIdx.x * blockDim.x + threadIdx.x;
    if (i >= N_ALL * DD) return;
    int row = i >> 8, col = i & 255;
    g_u[i] = g_pu[row * 512 + col] + expf(g_pu[row * 512 + 256 + col]) * nrm(rbits(k0, k1, i));
}
__global__ void k_sample_zM(unsigned k0, unsigned k1) {
    int i = blockIdx.x * blockDim.x + threadIdx.x;
    if (i >= NUM_M * DD) return;
    int m = i >> 8, col = i & 255;
    int r = (NUM_R + m) * 512;
    g_zM[i] = g_qz[r + col] + expf(g_qz[r + 256 + col]) * nrm(rbits(k0, k1, i));
}
__global__ void k_sample_zR(unsigned k0, unsigned k1) {
    int i = blockIdx.x * blockDim.x + threadIdx.x;
    if (i >= NUM_R * DD) return;
    int r = i >> 8, col = i & 255;
    g_zR[i] = g_qz[r * 512 + col] + expf(g_qz[r * 512 + 256 + col]) * nrm(rbits(k0, k1, i));
}

__global__ void k_attn(const float* __restrict__ pg, const int* __restrict__ yM,
                       unsigned k0, unsigned k1) {
    int m = blockIdx.x, r = threadIdx.x;     // 64 threads
    __shared__ float um[DD];
    __shared__ float d2s[NUM_R];
    __shared__ float red[NUM_R];
    for (int i = r; i < DD; i += 64) um[i] = g_u[(size_t)(NUM_R + m) * DD + i];
    __syncthreads();
    float d2 = 0.f;
    const float* ur = g_u + (size_t)r * DD;
    for (int dd = 0; dd < DD; dd++) {
        float t = um[dd] - ur[dd];
        d2 = fmaf(t, t, d2);
    }
    d2s[r] = d2;
    float logp = -0.5f * d2 / expf(pg[0]);
    float logit = logp - logf(fmaxf(-expm1f(logp), 1e-20f));
    float U = unif(rbits(k0, k1, (uint32_t)(m * NUM_R + r)));
    float gn = logf(U) - log1pf(-U);
    float A = 1.0f / (1.0f + expf(-(logit + gn) / 0.3f));
    red[r] = A;
    __syncthreads();
    for (int o = 32; o >= 1; o >>= 1) {
        if (r < o) red[r] += red[r + o];
        __syncthreads();
    }
    g_An[m * NUM_R + r] = A / (red[0] + 1e-8f);
    if (r < 32) {
        int idx = r + (1 - yM[m]) * 32;
        float t = sqrtf(fmaxf(d2s[idx], 1e-12f));
        for (int o = 16; o >= 1; o >>= 1) t += __shfl_down_sync(0xffffffffu, t, o);
        if (r == 0) atomicAdd(&g_acc[3], t);
    }
}

__global__ void k_pz() {
    int m = blockIdx.x, c = threadIdx.x;     // 256 threads
    __shared__ float an[NUM_R];
    if (c < NUM_R) an[c] = g_An[m * NUM_R + c];
    __syncthreads();
    float s0 = 0.f, s1 = 0.f;
    for (int r = 0; r < NUM_R; r++) {
        float a = an[r];
        s0 = fmaf(a, g_qz[r * 512 + c], s0);
        s1 = fmaf(a, g_qz[r * 512 + 256 + c], s1);
    }
    g_pzm[m * DD + c] = s0;
    g_pzl[m * DD + c] = s1;
}

__global__ void k_pqz() {
    int m = blockIdx.x, c = threadIdx.x;
    float z = g_zM[m * DD + c];
    float pm = g_pzm[m * DD + c], pl = g_pzl[m * DD + c];
    float qm = g_qz[(NUM_R + m) * 512 + c], ql = g_qz[(NUM_R + m) * 512 + 256 + c];
    float t1 = (z - pm) * expf(-pl);
    float t2 = (z - qm) * expf(-ql);
    float v = (-pl - 0.5f * t1 * t1) - (-ql - 0.5f * t2 * t2);
    __shared__ float red[256];
    red[c] = v;
    __syncthreads();
    for (int o = 128; o >= 1; o >>= 1) {
        if (c < o) red[c] += red[c + o];
        __syncthreads();
    }
    if (c == 0) atomicAdd(&g_acc[1], red[0]);
}

__global__ void k_repM() {
    int i = blockIdx.x * blockDim.x + threadIdx.x;
    if (i >= NUM_M * 512) return;
    int m = i >> 9, c = i & 511;
    g_repM[i] = (c < 256) ? g_zM[m * DD + c] : g_u[(size_t)(NUM_R + m) * DD + (c - 256)];
}
__global__ void k_repR() {
    int i = blockIdx.x * blockDim.x + threadIdx.x;
    if (i >= NUM_R * 512) return;
    int r = i >> 9, c = i & 511;
    g_repR[i] = (c < 256) ? g_zR[r * DD + c] : g_u[(size_t)r * DD + (c - 256)];
}

__global__ void k_head(const float* __restrict__ hid, const float* __restrict__ W2,
                       const float* __restrict__ b2, const int* __restrict__ y,
                       int rows, int accIdx) {
    int gw = (blockIdx.x * blockDim.x + threadIdx.x) >> 5;
    int lane = threadIdx.x & 31;
    if (gw >= rows) return;
    float p0 = 0.f, p1 = 0.f;
#pragma unroll
    for (int j = 0; j < 8; j++) {
        int k = lane + 32 * j;
        float h = hid[(size_t)gw * 256 + k];
        p0 = fmaf(h, W2[k * 2], p0);
        p1 = fmaf(h, W2[k * 2 + 1], p1);
    }
    for (int o = 16; o >= 1; o >>= 1) {
        p0 += __shfl_down_sync(0xffffffffu, p0, o);
        p1 += __shfl_down_sync(0xffffffffu, p1, o);
    }
    if (lane == 0) {
        float l0 = p0 + b2[0], l1 = p1 + b2[1];
        float mx = fmaxf(l0, l1);
        float lse = mx + logf(expf(l0 - mx) + expf(l1 - mx));
        atomicAdd(&g_acc[accIdx], ((y[gw] != 0) ? l1 : l0) - lse);
    }
}

__global__ void k_final(float* __restrict__ out) {
    float pred = -(g_acc[0] + 0.1f * g_acc[1]) / 1024.0f;
    float rat  = -g_acc[2] / 64.0f;
    float reg  = g_acc[3] / 32768.0f;
    out[0] = pred + rat - 0.1f * reg;
}

extern "C" void kernel_launch(void* const* d_in, const int* in_sizes, int n_in,
                              void* d_out, int out_size) {
    (void)in_sizes; (void)n_in; (void)out_size;
    const float* x     = (const float*)d_in[0];
    const int*   ei    = (const int*)  d_in[1];
    const int*   et    = (const int*)  d_in[2];
    const int*   batch = (const int*)  d_in[3];
    const int*   yM    = (const int*)  d_in[4];
    const int*   yR    = (const int*)  d_in[5];
    const float* HR    = (const float*)d_in[6];
    const float* nodeW = (const float*)d_in[7];
    const float* nodeB = (const float*)d_in[8];
    const float* Wr    = (const float*)d_in[9];
    const float* Wroot = (const float*)d_in[10];
    const float* gcnB  = (const float*)d_in[11];
    const float* pg    = (const float*)d_in[12];
    const float* puW   = (const float*)d_in[13];
    const float* puB   = (const float*)d_in[14];
    const float* qzW   = (const float*)d_in[15];
    const float* qzB   = (const float*)d_in[16];
    const float* W1    = (const float*)d_in[17];
    const float* b1    = (const float*)d_in[18];
    const float* W2    = (const float*)d_in[19];
    const float* b2    = (const float*)d_in[20];
    float* out = (float*)d_out;

    // key(42) = (0,42); partitionable split: key_i = tf2x32(key, 0, i)
    uint32_t ku0, ku1, ka0, ka1, kzm0, kzm1, kzr0, kzr1;
    tf2x32(0u, 42u, 0u, 0u, ku0, ku1);
    tf2x32(0u, 42u, 0u, 1u, ka0, ka1);
    tf2x32(0u, 42u, 0u, 2u, kzm0, kzm1);
    tf2x32(0u, 42u, 0u, 3u, kzr0, kzr1);

    void* p;
    cudaGetSymbolAddress(&p, g_featsA); float* featsA = (float*)p;
    cudaGetSymbolAddress(&p, g_featsB); float* featsB = (float*)p;
    cudaGetSymbolAddress(&p, g_G);      float* G      = (float*)p;
    cudaGetSymbolAddress(&p, g_Wcat);   float* Wcat   = (float*)p;
    cudaGetSymbolAddress(&p, g_Hall);   float* Hall   = (float*)p;
    cudaGetSymbolAddress(&p, g_pu);     float* pu     = (float*)p;
    cudaGetSymbolAddress(&p, g_qz);     float* qz     = (float*)p;
    cudaGetSymbolAddress(&p, g_repM);   float* repM   = (float*)p;
    cudaGetSymbolAddress(&p, g_repR);   float* repR   = (float*)p;
    cudaGetSymbolAddress(&p, g_hidM);   float* hidM   = (float*)p;
    cudaGetSymbolAddress(&p, g_hidR);   float* hidR   = (float*)p;

    k_zero_init<<<(N_RELS * N_NODES + 255) / 256, 256>>>();
    k_count<<<(N_EDGES + 255) / 256, 256>>>(ei, et);
    k_scan<<<1, 1024>>>();
    k_cursor<<<(N_NODES + 255) / 256, 256>>>();
    k_scatter<<<(N_EDGES + 255) / 256, 256>>>(ei);
    k_wcat<<<(N_LAYERS * 256 * GW + 255) / 256, 256>>>(Wroot, Wr);

    k_sgemm<<<dim3(2, (N_NODES + 127) / 128), 256>>>(
        x, nodeW, nodeB, featsA, N_NODES, 256, D_IN, 0, 0);

    float* cur = featsA;
    float* nxt = featsB;
    for (int l = 0; l < N_LAYERS; l++) {
        k_sgemm<<<dim3(GW / 128, (N_NODES + 127) / 128), 256>>>(
            cur, Wcat + (size_t)l * 256 * GW, nullptr, G, N_NODES, GW, 256, 0, 0);
        k_agg<<<(N_NODES * 32 + 255) / 256, 256>>>(
            ei, et, gcnB + l * 256, nxt, (l < N_LAYERS - 1) ? 1 : 0);
        float* t = cur; cur = nxt; nxt = t;
    }

    k_starts<<<(NUM_M + 256) / 256, 256>>>(batch);
    k_copyHR<<<(NUM_R * DD + 255) / 256, 256>>>(HR);
    k_gmean<<<NUM_M, 256>>>(cur);

    k_sgemm<<<dim3(4, (N_ALL + 127) / 128), 256>>>(Hall, puW, puB, pu, N_ALL, 512, 256, 1, 0);
    k_sgemm<<<dim3(4, (N_ALL + 127) / 128), 256>>>(Hall, qzW, qzB, qz, N_ALL, 512, 256, 1, 0);

    k_sample_u <<<(N_ALL * DD + 255) / 256, 256>>>(ku0, ku1);
    k_sample_zM<<<(NUM_M * DD + 255) / 256, 256>>>(kzm0, kzm1);
    k_sample_zR<<<(NUM_R * DD + 255) / 256, 256>>>(kzr0, kzr1);

    k_attn<<<NUM_M, 64>>>(pg, yM, ka0, ka1);
    k_pz  <<<NUM_M, 256>>>();
    k_pqz <<<NUM_M, 256>>>();

    k_repM<<<(NUM_M * 512 + 255) / 256, 256>>>();
    k_repR<<<(NUM_R * 512 + 255) / 256, 256>>>();
    k_sgemm<<<dim3(2, (NUM_M + 127) / 128), 256>>>(repM, W1, b1, hidM, NUM_M, 256, 512, 0, 1);
    k_sgemm<<<dim3(2, 1), 256>>>(repR, W1, b1, hidR, NUM_R, 256, 512, 0, 1);
    k_head<<<(NUM_M * 32 + 255) / 256, 256>>>(hidM, W2, b2, yM, NUM_M, 0);
    k_head<<<(NUM_R * 32 + 255) / 256, 256>>>(hidR, W2, b2, yR, NUM_R, 2);

    k_final<<<1, 1>>>(out);
}

// round 3
// speedup vs baseline: 1.4477x; 1.4477x over previous
#include <cuda_runtime.h>
#include <cuda_bf16.h>
#include <stdint.h>
#include <math.h>

#define N_NODES 50000
#define N_EDGES 200000
#define D_IN    128
#define DD      256
#define N_LAYERS 4
#define N_RELS  4
#define NUM_M   1024
#define NUM_R   64
#define N_ALL   (NUM_R + NUM_M)
#define GW      1280

__device__ float g_featsA[N_NODES * DD];
__device__ float g_featsB[N_NODES * DD];
__device__ float g_G[(size_t)N_NODES * GW];
__device__ __nv_bfloat16 g_Wh[N_LAYERS * GW * 256];   // [l][n][k] transposed hi
__device__ __nv_bfloat16 g_Wl[N_LAYERS * GW * 256];   // lo
__device__ int   g_cnt[N_RELS * N_NODES];
__device__ int   g_deg[N_NODES];
__device__ int   g_off[N_NODES + 1];
__device__ int   g_cursor[N_NODES];
__device__ int   g_esort[N_EDGES];
__device__ int   g_start[NUM_M + 1];
__device__ float g_Hall[N_ALL * DD];
__device__ float g_pu[N_ALL * 512];
__device__ float g_qz[N_ALL * 512];
__device__ float g_u[N_ALL * DD];
__device__ float g_zM[NUM_M * DD];
__device__ float g_zR[NUM_R * DD];
__device__ float g_An[NUM_M * NUM_R];
__device__ float g_pzm[NUM_M * DD];
__device__ float g_pzl[NUM_M * DD];
__device__ float g_repM[NUM_M * 512];
__device__ float g_repR[NUM_R * 512];
__device__ float g_hidM[NUM_M * 256];
__device__ float g_hidR[NUM_R * 256];
__device__ float g_acc[4];

__host__ __device__ __forceinline__ uint32_t rotl32(uint32_t x, int d) {
    return (x << d) | (x >> (32 - d));
}
__host__ __device__ __forceinline__ void tf2x32(uint32_t k0, uint32_t k1,
                                                uint32_t x0, uint32_t x1,
                                                uint32_t& o0, uint32_t& o1) {
    uint32_t ks2 = k0 ^ k1 ^ 0x1BD11BDAu;
    x0 += k0; x1 += k1;
#define TF_RND(R) { x0 += x1; x1 = rotl32(x1, R); x1 ^= x0; }
    TF_RND(13) TF_RND(15) TF_RND(26) TF_RND(6)
    x0 += k1;  x1 += ks2 + 1u;
    TF_RND(17) TF_RND(29) TF_RND(16) TF_RND(24)
    x0 += ks2; x1 += k0 + 2u;
    TF_RND(13) TF_RND(15) TF_RND(26) TF_RND(6)
    x0 += k0;  x1 += k1 + 3u;
    TF_RND(17) TF_RND(29) TF_RND(16) TF_RND(24)
    x0 += k1;  x1 += ks2 + 4u;
    TF_RND(13) TF_RND(15) TF_RND(26) TF_RND(6)
    x0 += ks2; x1 += k0 + 5u;
#undef TF_RND
    o0 = x0; o1 = x1;
}
__device__ __forceinline__ uint32_t rbits(uint32_t k0, uint32_t k1, uint32_t i) {
    uint32_t o0, o1; tf2x32(k0, k1, 0u, i, o0, o1); return o0 ^ o1;
}
__device__ __forceinline__ float erfinv_xla(float x) {
    float w = -log1pf(-x * x), p;
    if (w < 5.0f) {
        w -= 2.5f;
        p = 2.81022636e-08f;
        p = fmaf(p, w, 3.43273939e-07f);  p = fmaf(p, w, -3.5233877e-06f);
        p = fmaf(p, w, -4.39150654e-06f); p = fmaf(p, w, 0.00021858087f);
        p = fmaf(p, w, -0.00125372503f);  p = fmaf(p, w, -0.00417768164f);
        p = fmaf(p, w, 0.246640727f);     p = fmaf(p, w, 1.50140941f);
    } else {
        w = sqrtf(w) - 3.0f;
        p = -0.000200214257f;
        p = fmaf(p, w, 0.000100950558f);  p = fmaf(p, w, 0.00134934322f);
        p = fmaf(p, w, -0.00367342844f);  p = fmaf(p, w, 0.00573950773f);
        p = fmaf(p, w, -0.0076224613f);   p = fmaf(p, w, 0.00943887047f);
        p = fmaf(p, w, 1.00167406f);      p = fmaf(p, w, 2.83297682f);
    }
    return p * x;
}
__device__ __forceinline__ float u01(uint32_t b) {
    return __uint_as_float((b >> 9) | 0x3f800000u) - 1.0f;
}
__device__ __forceinline__ float nrm(uint32_t b) {
    const float LO = -0.99999994f;
    float v = u01(b) * 2.0f + LO;
    v = fmaxf(LO, v);
    return 1.41421356f * erfinv_xla(v);
}
__device__ __forceinline__ float unif(uint32_t b) {
    const float MN = 1e-06f;
    float v = u01(b) * (0.999999f - MN) + MN;
    return fmaxf(MN, v);
}

__global__ void k_zero_init() {
    int i = blockIdx.x * blockDim.x + threadIdx.x;
    if (i < N_RELS * N_NODES) g_cnt[i] = 0;
    if (i < N_NODES) g_deg[i] = 0;
    if (i < 4) g_acc[i] = 0.0f;
}
__global__ void k_count(const int* __restrict__ ei, const int* __restrict__ et) {
    int e = blockIdx.x * blockDim.x + threadIdx.x;
    if (e >= N_EDGES) return;
    int d = ei[N_EDGES + e];
    atomicAdd(&g_cnt[et[e] * N_NODES + d], 1);
    atomicAdd(&g_deg[d], 1);
}
__global__ void k_scan() {
    __shared__ int part[1024];
    int tid = threadIdx.x;
    const int chunk = (N_NODES + 1023) / 1024;
    int lo = tid * chunk, hi = min(lo + chunk, N_NODES);
    int s = 0;
    for (int i = lo; i < hi; i++) s += g_deg[i];
    part[tid] = s;
    __syncthreads();
    for (int o = 1; o < 1024; o <<= 1) {
        int v = (tid >= o) ? part[tid - o] : 0;
        __syncthreads(); part[tid] += v; __syncthreads();
    }
    int run = part[tid] - s;
    for (int i = lo; i < hi; i++) { g_off[i] = run; run += g_deg[i]; }
    if (tid == 1023) g_off[N_NODES] = run;
}
__global__ void k_cursor() {
    int i = blockIdx.x * blockDim.x + threadIdx.x;
    if (i < N_NODES) g_cursor[i] = g_off[i];
}
__global__ void k_scatter(const int* __restrict__ ei) {
    int e = blockIdx.x * blockDim.x + threadIdx.x;
    if (e >= N_EDGES) return;
    int p = atomicAdd(&g_cursor[ei[N_EDGES + e]], 1);
    g_esort[p] = e;
}
// build transposed hi/lo bf16 weight panels: g_Wh[(l*GW+n)*256+k]
__global__ void k_wsplit(const float* __restrict__ Wroot, const float* __restrict__ Wr) {
    int idx = blockIdx.x * blockDim.x + threadIdx.x;
    if (idx >= N_LAYERS * GW * 256) return;
    int l = idx / (GW * 256), rem = idx % (GW * 256);
    int n = rem / 256, k = rem % 256;
    float v;
    if (n < 256) v = Wroot[((size_t)l * 256 + k) * 256 + n];
    else {
        int r = (n >> 8) - 1, h = n & 255;
        v = Wr[(((size_t)l * 4 + r) * 256 + k) * 256 + h];
    }
    __nv_bfloat16 hi = __float2bfloat16(v);
    g_Wh[idx] = hi;
    g_Wl[idx] = __float2bfloat16(v - __bfloat162float(hi));
}

// ---------------- bf16 tensor-core GEMM (3-term split), BM=BN=128, BK=32 ----------------
__device__ __forceinline__ void ldm4(uint32_t a, uint32_t& r0, uint32_t& r1,
                                     uint32_t& r2, uint32_t& r3) {
    asm volatile("ldmatrix.sync.aligned.m8n8.x4.shared.b16 {%0,%1,%2,%3}, [%4];"
                 : "=r"(r0), "=r"(r1), "=r"(r2), "=r"(r3) : "r"(a));
}
__device__ __forceinline__ void mma16816(float* c, const uint32_t* a, const uint32_t* b) {
    asm volatile("mma.sync.aligned.m16n8k16.row.col.f32.bf16.bf16.f32 "
                 "{%0,%1,%2,%3},{%4,%5,%6,%7},{%8,%9},{%0,%1,%2,%3};"
                 : "+f"(c[0]), "+f"(c[1]), "+f"(c[2]), "+f"(c[3])
                 : "r"(a[0]), "r"(a[1]), "r"(a[2]), "r"(a[3]), "r"(b[0]), "r"(b[1]));
}

__global__ void __launch_bounds__(256, 1)
k_bmma(const float* __restrict__ A, const __nv_bfloat16* __restrict__ Bh,
       const __nv_bfloat16* __restrict__ Bl, const float* __restrict__ bias,
       float* __restrict__ C, int M, int N, int K, int relu_out) {
    __shared__ __nv_bfloat16 Ah[128 * 40], Al[128 * 40], Bhs[128 * 40], Bls[128 * 40];
    int tid = threadIdx.x, lane = tid & 31, wid = tid >> 5;
    int wm = (wid >> 2) * 64, wn = (wid & 3) * 32;
    int bm = blockIdx.y * 128, bn = blockIdx.x * 128;
    float acc[4][4][4];
#pragma unroll
    for (int i = 0; i < 4; i++)
#pragma unroll
        for (int j = 0; j < 4; j++)
#pragma unroll
            for (int q = 0; q < 4; q++) acc[i][j][q] = 0.f;

    int row = tid >> 1, cb = (tid & 1) * 16;
    uint32_t sb = (uint32_t)__cvta_generic_to_shared(Ah);
    uint32_t sbl = (uint32_t)__cvta_generic_to_shared(Al);
    uint32_t sbh = (uint32_t)__cvta_generic_to_shared(Bhs);
    uint32_t sbb = (uint32_t)__cvta_generic_to_shared(Bls);

    for (int k0 = 0; k0 < K; k0 += 32) {
        // stage A (fp32 -> hi/lo bf16)
        {
            float v[16];
            int rg = bm + row;
            if (rg < M) {
                const float4* p = (const float4*)(A + (size_t)rg * K + k0 + cb);
#pragma unroll
                for (int j = 0; j < 4; j++) {
                    float4 f = p[j];
                    v[j * 4 + 0] = f.x; v[j * 4 + 1] = f.y; v[j * 4 + 2] = f.z; v[j * 4 + 3] = f.w;
                }
            } else {
#pragma unroll
                for (int j = 0; j < 16; j++) v[j] = 0.f;
            }
#pragma unroll
            for (int j = 0; j < 8; j++) {
                __nv_bfloat16 h0 = __float2bfloat16(v[2 * j]);
                __nv_bfloat16 h1 = __float2bfloat16(v[2 * j + 1]);
                __nv_bfloat162 hp; hp.x = h0; hp.y = h1;
                *(__nv_bfloat162*)&Ah[row * 40 + cb + 2 * j] = hp;
                __nv_bfloat162 lp;
                lp.x = __float2bfloat16(v[2 * j] - __bfloat162float(h0));
                lp.y = __float2bfloat16(v[2 * j + 1] - __bfloat162float(h1));
                *(__nv_bfloat162*)&Al[row * 40 + cb + 2 * j] = lp;
            }
        }
        // stage B (already bf16, [n][K])
        {
            const uint4* ph = (const uint4*)(Bh + (size_t)(bn + row) * K + k0 + cb);
            const uint4* pl = (const uint4*)(Bl + (size_t)(bn + row) * K + k0 + cb);
            uint4* dh = (uint4*)&Bhs[row * 40 + cb];
            uint4* dl = (uint4*)&Bls[row * 40 + cb];
            dh[0] = ph[0]; dh[1] = ph[1];
            dl[0] = pl[0]; dl[1] = pl[1];
        }
        __syncthreads();
#pragma unroll
        for (int kk = 0; kk < 32; kk += 16) {
            uint32_t ah[4][4], al[4][4], bh[4][2], bl[4][2];
            int arow = wm + (lane & 7) + ((lane >> 3) & 1) * 8;
            int acol = kk + ((lane >> 4) & 1) * 8;
#pragma unroll
            for (int mf = 0; mf < 4; mf++) {
                uint32_t off = ((arow + mf * 16) * 40 + acol) * 2;
                ldm4(sb + off, ah[mf][0], ah[mf][1], ah[mf][2], ah[mf][3]);
                ldm4(sbl + off, al[mf][0], al[mf][1], al[mf][2], al[mf][3]);
            }
            int brow = wn + (lane & 7) + ((lane >> 4) & 1) * 8;
            int bcol = kk + ((lane >> 3) & 1) * 8;
#pragma unroll
            for (int nb = 0; nb < 2; nb++) {
                uint32_t off = ((brow + nb * 16) * 40 + bcol) * 2;
                ldm4(sbh + off, bh[2 * nb][0], bh[2 * nb][1], bh[2 * nb + 1][0], bh[2 * nb + 1][1]);
                ldm4(sbb + off, bl[2 * nb][0], bl[2 * nb][1], bl[2 * nb + 1][0], bl[2 * nb + 1][1]);
            }
#pragma unroll
            for (int mf = 0; mf < 4; mf++)
#pragma unroll
                for (int nf = 0; nf < 4; nf++) {
                    mma16816(acc[mf][nf], ah[mf], bh[nf]);
                    mma16816(acc[mf][nf], ah[mf], bl[nf]);
                    mma16816(acc[mf][nf], al[mf], bh[nf]);
                }
        }
        __syncthreads();
    }
#pragma unroll
    for (int mf = 0; mf < 4; mf++)
#pragma unroll
        for (int nf = 0; nf < 4; nf++) {
            int r0 = bm + wm + mf * 16 + (lane >> 2);
            int c0 = bn + wn + nf * 8 + (lane & 3) * 2;
#pragma unroll
            for (int h = 0; h < 2; h++) {
                int r = r0 + h * 8;
                if (r >= M) continue;
                float v0 = acc[mf][nf][2 * h], v1 = acc[mf][nf][2 * h + 1];
                if (bias) { v0 += bias[c0]; v1 += bias[c0 + 1]; }
                if (relu_out) { v0 = fmaxf(v0, 0.f); v1 = fmaxf(v1, 0.f); }
                *(float2*)(C + (size_t)r * N + c0) = make_float2(v0, v1);
            }
        }
}

__global__ void __launch_bounds__(256)
k_sgemm(const float* __restrict__ A, const float* __restrict__ B,
        const float* __restrict__ bias, float* __restrict__ C,
        int M, int N, int K, int relu_in, int relu_out) {
    __shared__ float As[8][128];
    __shared__ float Bs[8][128];
    int bm = blockIdx.y * 128, bn = blockIdx.x * 128;
    int tid = threadIdx.x, tr = tid >> 4, tc = tid & 15;
    float acc[8][8];
#pragma unroll
    for (int i = 0; i < 8; i++)
#pragma unroll
        for (int j = 0; j < 8; j++) acc[i][j] = 0.f;
    int aRow = tid >> 1, aCol = (tid & 1) * 4;
    int bRow = tid >> 5, bCol = (tid & 31) * 4;
    for (int k0 = 0; k0 < K; k0 += 8) {
        float4 av = make_float4(0.f, 0.f, 0.f, 0.f);
        if (bm + aRow < M)
            av = *(const float4*)(A + (size_t)(bm + aRow) * K + k0 + aCol);
        if (relu_in) {
            av.x = fmaxf(av.x, 0.f); av.y = fmaxf(av.y, 0.f);
            av.z = fmaxf(av.z, 0.f); av.w = fmaxf(av.w, 0.f);
        }
        As[aCol + 0][aRow] = av.x; As[aCol + 1][aRow] = av.y;
        As[aCol + 2][aRow] = av.z; As[aCol + 3][aRow] = av.w;
        float4 bv = make_float4(0.f, 0.f, 0.f, 0.f);
        if (bn + bCol < N)
            bv = *(const float4*)(B + (size_t)(k0 + bRow) * N + bn + bCol);
        *(float4*)&Bs[bRow][bCol] = bv;
        __syncthreads();
#pragma unroll
        for (int kk = 0; kk < 8; kk++) {
            float a[8], b[8];
            *(float4*)(a)     = *(const float4*)&As[kk][tr * 8];
            *(float4*)(a + 4) = *(const float4*)&As[kk][tr * 8 + 4];
            *(float4*)(b)     = *(const float4*)&Bs[kk][tc * 8];
            *(float4*)(b + 4) = *(const float4*)&Bs[kk][tc * 8 + 4];
#pragma unroll
            for (int i = 0; i < 8; i++)
#pragma unroll
                for (int j = 0; j < 8; j++) acc[i][j] = fmaf(a[i], b[j], acc[i][j]);
        }
        __syncthreads();
    }
#pragma unroll
    for (int i = 0; i < 8; i++) {
        int row = bm + tr * 8 + i;
        if (row >= M) continue;
#pragma unroll
        for (int j = 0; j < 8; j++) {
            int col = bn + tc * 8 + j;
            if (col >= N) continue;
            float v = acc[i][j];
            if (bias) v += bias[col];
            if (relu_out) v = fmaxf(v, 0.f);
            C[(size_t)row * N + col] = v;
        }
    }
}

__global__ void k_agg(const int* __restrict__ ei, const int* __restrict__ et,
                      const float* __restrict__ bias, float* __restrict__ out, int relu) {
    int d = (blockIdx.x * blockDim.x + threadIdx.x) >> 5;
    int lane = threadIdx.x & 31;
    if (d >= N_NODES) return;
    float acc[8];
    const float* g0 = g_G + (size_t)d * GW;
#pragma unroll
    for (int j = 0; j < 8; j++) acc[j] = g0[lane + 32 * j] + bias[lane + 32 * j];
    int s = g_off[d], e = g_off[d + 1];
    for (int i = s; i < e; i++) {
        int eid = g_esort[i];
        int sn = ei[eid], r = et[eid];
        float inv = 1.0f / (float)g_cnt[r * N_NODES + d];
        const float* gp = g_G + (size_t)sn * GW + 256 + (r << 8);
#pragma unroll
        for (int j = 0; j < 8; j++) acc[j] = fmaf(gp[lane + 32 * j], inv, acc[j]);
    }
#pragma unroll
    for (int j = 0; j < 8; j++) {
        float v = acc[j];
        if (relu) v = fmaxf(v, 0.f);
        out[(size_t)d * DD + lane + 32 * j] = v;
    }
}

__global__ void k_starts(const int* __restrict__ batch) {
    int m = blockIdx.x * blockDim.x + threadIdx.x;
    if (m > NUM_M) return;
    int lo = 0, hi = N_NODES;
    while (lo < hi) { int mid = (lo + hi) >> 1; if (batch[mid] < m) lo = mid + 1; else hi = mid; }
    g_start[m] = lo;
}
__global__ void k_copyHR(const float* __restrict__ HR) {
    int i = blockIdx.x * blockDim.x + threadIdx.x;
    if (i < NUM_R * DD) g_Hall[i] = HR[i];
}
__global__ void k_gmean(const float* __restrict__ feats) {
    int m = blockIdx.x, c = threadIdx.x;
    int s = g_start[m], e = g_start[m + 1];
    float acc = 0.f;
    for (int n = s; n < e; n++) acc += feats[(size_t)n * DD + c];
    g_Hall[(size_t)(NUM_R + m) * DD + c] = acc / fmaxf((float)(e - s), 1.0f);
}

__global__ void k_sample_u(unsigned k0, unsigned k1) {
    int i = blockIdx.x * blockDim.x + threadIdx.x;
    if (i >= N_ALL * DD) return;
    int row = i >> 8, col = i & 255;
    g_u[i] = g_pu[row * 512 + col] + expf(g_pu[row * 512 + 256 + col]) * nrm(rbits(k0, k1, i));
}
__global__ void k_sample_zM(unsigned k0, unsigned k1) {
    int i = blockIdx.x * blockDim.x + threadIdx.x;
    if (i >= NUM_M * DD) return;
    int m = i >> 8, col = i & 255;
    int r = (NUM_R + m) * 512;
    g_zM[i] = g_qz[r + col] + expf(g_qz[r + 256 + col]) * nrm(rbits(k0, k1, i));
}
__global__ void k_sample_zR(unsigned k0, unsigned k1) {
    int i = blockIdx.x * blockDim.x + threadIdx.x;
    if (i >= NUM_R * DD) return;
    int r = i >> 8, col = i & 255;
    g_zR[i] = g_qz[r * 512 + col] + expf(g_qz[r * 512 + 256 + col]) * nrm(rbits(k0, k1, i));
}

__global__ void k_attn(const float* __restrict__ pg, const int* __restrict__ yM,
                       unsigned k0, unsigned k1) {
    int m = blockIdx.x, r = threadIdx.x;
    __shared__ float um[DD];
    __shared__ float d2s[NUM_R];
    __shared__ float red[NUM_R];
    for (int i = r; i < DD; i += 64) um[i] = g_u[(size_t)(NUM_R + m) * DD + i];
    __syncthreads();
    float d2 = 0.f;
    const float* ur = g_u + (size_t)r * DD;
    for (int dd = 0; dd < DD; dd++) {
        float t = um[dd] - ur[dd];
        d2 = fmaf(t, t, d2);
    }
    d2s[r] = d2;
    float logp = -0.5f * d2 / expf(pg[0]);
    float logit = logp - logf(fmaxf(-expm1f(logp), 1e-20f));
    float U = unif(rbits(k0, k1, (uint32_t)(m * NUM_R + r)));
    float gn = logf(U) - log1pf(-U);
    float A = 1.0f / (1.0f + expf(-(logit + gn) / 0.3f));
    red[r] = A;
    __syncthreads();
    for (int o = 32; o >= 1; o >>= 1) {
        if (r < o) red[r] += red[r + o];
        __syncthreads();
    }
    g_An[m * NUM_R + r] = A / (red[0] + 1e-8f);
    if (r < 32) {
        int idx = r + (1 - yM[m]) * 32;
        float t = sqrtf(fmaxf(d2s[idx], 1e-12f));
        for (int o = 16; o >= 1; o >>= 1) t += __shfl_down_sync(0xffffffffu, t, o);
        if (r == 0) atomicAdd(&g_acc[3], t);
    }
}

__global__ void k_pz() {
    int m = blockIdx.x, c = threadIdx.x;
    __shared__ float an[NUM_R];
    if (c < NUM_R) an[c] = g_An[m * NUM_R + c];
    __syncthreads();
    float s0 = 0.f, s1 = 0.f;
    for (int r = 0; r < NUM_R; r++) {
        float a = an[r];
        s0 = fmaf(a, g_qz[r * 512 + c], s0);
        s1 = fmaf(a, g_qz[r * 512 + 256 + c], s1);
    }
    g_pzm[m * DD + c] = s0;
    g_pzl[m * DD + c] = s1;
}

__global__ void k_pqz() {
    int m = blockIdx.x, c = threadIdx.x;
    float z = g_zM[m * DD + c];
    float pm = g_pzm[m * DD + c], pl = g_pzl[m * DD + c];
    float qm = g_qz[(NUM_R + m) * 512 + c], ql = g_qz[(NUM_R + m) * 512 + 256 + c];
    float t1 = (z - pm) * expf(-pl);
    float t2 = (z - qm) * expf(-ql);
    float v = (-pl - 0.5f * t1 * t1) - (-ql - 0.5f * t2 * t2);
    __shared__ float red[256];
    red[c] = v;
    __syncthreads();
    for (int o = 128; o >= 1; o >>= 1) {
        if (c < o) red[c] += red[c + o];
        __syncthreads();
    }
    if (c == 0) atomicAdd(&g_acc[1], red[0]);
}

__global__ void k_repM() {
    int i = blockIdx.x * blockDim.x + threadIdx.x;
    if (i >= NUM_M * 512) return;
    int m = i >> 9, c = i & 511;
    g_repM[i] = (c < 256) ? g_zM[m * DD + c] : g_u[(size_t)(NUM_R + m) * DD + (c - 256)];
}
__global__ void k_repR() {
    int i = blockIdx.x * blockDim.x + threadIdx.x;
    if (i >= NUM_R * 512) return;
    int r = i >> 9, c = i & 511;
    g_repR[i] = (c < 256) ? g_zR[r * DD + c] : g_u[(size_t)r * DD + (c - 256)];
}

__global__ void k_head(const float* __restrict__ hid, const float* __restrict__ W2,
                       const float* __restrict__ b2, const int* __restrict__ y,
                       int rows, int accIdx) {
    int gw = (blockIdx.x * blockDim.x + threadIdx.x) >> 5;
    int lane = threadIdx.x & 31;
    if (gw >= rows) return;
    float p0 = 0.f, p1 = 0.f;
#pragma unroll
    for (int j = 0; j < 8; j++) {
        int k = lane + 32 * j;
        float h = hid[(size_t)gw * 256 + k];
        p0 = fmaf(h, W2[k * 2], p0);
        p1 = fmaf(h, W2[k * 2 + 1], p1);
    }
    for (int o = 16; o >= 1; o >>= 1) {
        p0 += __shfl_down_sync(0xffffffffu, p0, o);
        p1 += __shfl_down_sync(0xffffffffu, p1, o);
    }
    if (lane == 0) {
        float l0 = p0 + b2[0], l1 = p1 + b2[1];
        float mx = fmaxf(l0, l1);
        float lse = mx + logf(expf(l0 - mx) + expf(l1 - mx));
        atomicAdd(&g_acc[accIdx], ((y[gw] != 0) ? l1 : l0) - lse);
    }
}

__global__ void k_final(float* __restrict__ out) {
    float pred = -(g_acc[0] + 0.1f * g_acc[1]) / 1024.0f;
    float rat  = -g_acc[2] / 64.0f;
    float reg  = g_acc[3] / 32768.0f;
    out[0] = pred + rat - 0.1f * reg;
}

extern "C" void kernel_launch(void* const* d_in, const int* in_sizes, int n_in,
                              void* d_out, int out_size) {
    (void)in_sizes; (void)n_in; (void)out_size;
    const float* x     = (const float*)d_in[0];
    const int*   ei    = (const int*)  d_in[1];
    const int*   et    = (const int*)  d_in[2];
    const int*   batch = (const int*)  d_in[3];
    const int*   yM    = (const int*)  d_in[4];
    const int*   yR    = (const int*)  d_in[5];
    const float* HR    = (const float*)d_in[6];
    const float* nodeW = (const float*)d_in[7];
    const float* nodeB = (const float*)d_in[8];
    const float* Wr    = (const float*)d_in[9];
    const float* Wroot = (const float*)d_in[10];
    const float* gcnB  = (const float*)d_in[11];
    const float* pg    = (const float*)d_in[12];
    const float* puW   = (const float*)d_in[13];
    const float* puB   = (const float*)d_in[14];
    const float* qzW   = (const float*)d_in[15];
    const float* qzB   = (const float*)d_in[16];
    const float* W1    = (const float*)d_in[17];
    const float* b1    = (const float*)d_in[18];
    const float* W2    = (const float*)d_in[19];
    const float* b2    = (const float*)d_in[20];
    float* out = (float*)d_out;

    uint32_t ku0, ku1, ka0, ka1, kzm0, kzm1, kzr0, kzr1;
    tf2x32(0u, 42u, 0u, 0u, ku0, ku1);
    tf2x32(0u, 42u, 0u, 1u, ka0, ka1);
    tf2x32(0u, 42u, 0u, 2u, kzm0, kzm1);
    tf2x32(0u, 42u, 0u, 3u, kzr0, kzr1);

    void* p;
    cudaGetSymbolAddress(&p, g_featsA); float* featsA = (float*)p;
    cudaGetSymbolAddress(&p, g_featsB); float* featsB = (float*)p;
    cudaGetSymbolAddress(&p, g_G);      float* G      = (float*)p;
    cudaGetSymbolAddress(&p, g_Wh);     __nv_bfloat16* Wh = (__nv_bfloat16*)p;
    cudaGetSymbolAddress(&p, g_Wl);     __nv_bfloat16* Wl = (__nv_bfloat16*)p;
    cudaGetSymbolAddress(&p, g_Hall);   float* Hall   = (float*)p;
    cudaGetSymbolAddress(&p, g_pu);     float* pu     = (float*)p;
    cudaGetSymbolAddress(&p, g_qz);     float* qz     = (float*)p;
    cudaGetSymbolAddress(&p, g_repM);   float* repM   = (float*)p;
    cudaGetSymbolAddress(&p, g_repR);   float* repR   = (float*)p;
    cudaGetSymbolAddress(&p, g_hidM);   float* hidM   = (float*)p;
    cudaGetSymbolAddress(&p, g_hidR);   float* hidR   = (float*)p;

    k_zero_init<<<(N_RELS * N_NODES + 255) / 256, 256>>>();
    k_count<<<(N_EDGES + 255) / 256, 256>>>(ei, et);
    k_scan<<<1, 1024>>>();
    k_cursor<<<(N_NODES + 255) / 256, 256>>>();
    k_scatter<<<(N_EDGES + 255) / 256, 256>>>(ei);
    k_wsplit<<<(N_LAYERS * GW * 256 + 255) / 256, 256>>>(Wroot, Wr);

    k_sgemm<<<dim3(2, (N_NODES + 127) / 128), 256>>>(
        x, nodeW, nodeB, featsA, N_NODES, 256, D_IN, 0, 0);

    float* cur = featsA;
    float* nxt = featsB;
    for (int l = 0; l < N_LAYERS; l++) {
        k_bmma<<<dim3(GW / 128, (N_NODES + 127) / 128), 256>>>(
            cur, Wh + (size_t)l * GW * 256, Wl + (size_t)l * GW * 256,
            nullptr, G, N_NODES, GW, 256, 0);
        k_agg<<<(N_NODES * 32 + 255) / 256, 256>>>(
            ei, et, gcnB + l * 256, nxt, (l < N_LAYERS - 1) ? 1 : 0);
        float* t = cur; cur = nxt; nxt = t;
    }

    k_starts<<<(NUM_M + 256) / 256, 256>>>(batch);
    k_copyHR<<<(NUM_R * DD + 255) / 256, 256>>>(HR);
    k_gmean<<<NUM_M, 256>>>(cur);

    k_sgemm<<<dim3(4, (N_ALL + 127) / 128), 256>>>(Hall, puW, puB, pu, N_ALL, 512, 256, 1, 0);
    k_sgemm<<<dim3(4, (N_ALL + 127) / 128), 256>>>(Hall, qzW, qzB, qz, N_ALL, 512, 256, 1, 0);

    k_sample_u <<<(N_ALL * DD + 255) / 256, 256>>>(ku0, ku1);
    k_sample_zM<<<(NUM_M * DD + 255) / 256, 256>>>(kzm0, kzm1);
    k_sample_zR<<<(NUM_R * DD + 255) / 256, 256>>>(kzr0, kzr1);

    k_attn<<<NUM_M, 64>>>(pg, yM, ka0, ka1);
    k_pz  <<<NUM_M, 256>>>();
    k_pqz <<<NUM_M, 256>>>();

    k_repM<<<(NUM_M * 512 + 255) / 256, 256>>>();
    k_repR<<<(NUM_R * 512 + 255) / 256, 256>>>();
    k_sgemm<<<dim3(2, (NUM_M + 127) / 128), 256>>>(repM, W1, b1, hidM, NUM_M, 256, 512, 0, 1);
    k_sgemm<<<dim3(2, 1), 256>>>(repR, W1, b1, hidR, NUM_R, 256, 512, 0, 1);
    k_head<<<(NUM_M * 32 + 255) / 256, 256>>>(hidM, W2, b2, yM, NUM_M, 0);
    k_head<<<(NUM_R * 32 + 255) / 256, 256>>>(hidR, W2, b2, yR, NUM_R, 2);

    k_final<<<1, 1>>>(out);
}

// round 4
// speedup vs baseline: 1.8066x; 1.2480x over previous
#include <cuda_runtime.h>
#include <cuda_bf16.h>
#include <stdint.h>
#include <math.h>

#define N_NODES 50000
#define N_EDGES 200000
#define D_IN    128
#define DD      256
#define N_LAYERS 4
#define N_RELS  4
#define NUM_M   1024
#define NUM_R   64
#define N_ALL   (NUM_R + NUM_M)
#define GW      1280
#define MPAD    (N_NODES + 128)

__device__ float g_featsA[N_NODES * DD];
__device__ float g_featsB[N_NODES * DD];
__device__ float g_G[(size_t)N_NODES * GW];
__device__ __nv_bfloat16 g_Wh[N_LAYERS * GW * 256];
__device__ __nv_bfloat16 g_Wl[N_LAYERS * GW * 256];
__device__ __nv_bfloat16 g_nWh[256 * D_IN];
__device__ __nv_bfloat16 g_nWl[256 * D_IN];
__device__ __nv_bfloat16 g_xh[(size_t)MPAD * D_IN];
__device__ __nv_bfloat16 g_xl[(size_t)MPAD * D_IN];
__device__ __nv_bfloat16 g_Ah[(size_t)MPAD * DD];
__device__ __nv_bfloat16 g_Al[(size_t)MPAD * DD];
__device__ int   g_cnt[N_RELS * N_NODES];
__device__ int   g_deg[N_NODES];
__device__ int   g_off[N_NODES + 1];
__device__ int   g_cursor[N_NODES];
__device__ int   g_esort[N_EDGES];
__device__ int   g_start[NUM_M + 1];
__device__ float g_Hall[N_ALL * DD];
__device__ float g_pu[N_ALL * 512];
__device__ float g_qz[N_ALL * 512];
__device__ float g_u[N_ALL * DD];
__device__ float g_zM[NUM_M * DD];
__device__ float g_zR[NUM_R * DD];
__device__ float g_An[NUM_M * NUM_R];
__device__ float g_pzm[NUM_M * DD];
__device__ float g_pzl[NUM_M * DD];
__device__ float g_repM[NUM_M * 512];
__device__ float g_repR[NUM_R * 512];
__device__ float g_hidM[NUM_M * 256];
__device__ float g_hidR[NUM_R * 256];
__device__ float g_acc[4];

__host__ __device__ __forceinline__ uint32_t rotl32(uint32_t x, int d) {
    return (x << d) | (x >> (32 - d));
}
__host__ __device__ __forceinline__ void tf2x32(uint32_t k0, uint32_t k1,
                                                uint32_t x0, uint32_t x1,
                                                uint32_t& o0, uint32_t& o1) {
    uint32_t ks2 = k0 ^ k1 ^ 0x1BD11BDAu;
    x0 += k0; x1 += k1;
#define TF_RND(R) { x0 += x1; x1 = rotl32(x1, R); x1 ^= x0; }
    TF_RND(13) TF_RND(15) TF_RND(26) TF_RND(6)
    x0 += k1;  x1 += ks2 + 1u;
    TF_RND(17) TF_RND(29) TF_RND(16) TF_RND(24)
    x0 += ks2; x1 += k0 + 2u;
    TF_RND(13) TF_RND(15) TF_RND(26) TF_RND(6)
    x0 += k0;  x1 += k1 + 3u;
    TF_RND(17) TF_RND(29) TF_RND(16) TF_RND(24)
    x0 += k1;  x1 += ks2 + 4u;
    TF_RND(13) TF_RND(15) TF_RND(26) TF_RND(6)
    x0 += ks2; x1 += k0 + 5u;
#undef TF_RND
    o0 = x0; o1 = x1;
}
__device__ __forceinline__ uint32_t rbits(uint32_t k0, uint32_t k1, uint32_t i) {
    uint32_t o0, o1; tf2x32(k0, k1, 0u, i, o0, o1); return o0 ^ o1;
}
__device__ __forceinline__ float erfinv_xla(float x) {
    float w = -log1pf(-x * x), p;
    if (w < 5.0f) {
        w -= 2.5f;
        p = 2.81022636e-08f;
        p = fmaf(p, w, 3.43273939e-07f);  p = fmaf(p, w, -3.5233877e-06f);
        p = fmaf(p, w, -4.39150654e-06f); p = fmaf(p, w, 0.00021858087f);
        p = fmaf(p, w, -0.00125372503f);  p = fmaf(p, w, -0.00417768164f);
        p = fmaf(p, w, 0.246640727f);     p = fmaf(p, w, 1.50140941f);
    } else {
        w = sqrtf(w) - 3.0f;
        p = -0.000200214257f;
        p = fmaf(p, w, 0.000100950558f);  p = fmaf(p, w, 0.00134934322f);
        p = fmaf(p, w, -0.00367342844f);  p = fmaf(p, w, 0.00573950773f);
        p = fmaf(p, w, -0.0076224613f);   p = fmaf(p, w, 0.00943887047f);
        p = fmaf(p, w, 1.00167406f);      p = fmaf(p, w, 2.83297682f);
    }
    return p * x;
}
__device__ __forceinline__ float u01(uint32_t b) {
    return __uint_as_float((b >> 9) | 0x3f800000u) - 1.0f;
}
__device__ __forceinline__ float nrm(uint32_t b) {
    const float LO = -0.99999994f;
    float v = u01(b) * 2.0f + LO;
    v = fmaxf(LO, v);
    return 1.41421356f * erfinv_xla(v);
}
__device__ __forceinline__ float unif(uint32_t b) {
    const float MN = 1e-06f;
    float v = u01(b) * (0.999999f - MN) + MN;
    return fmaxf(MN, v);
}

__global__ void k_zero_init() {
    int i = blockIdx.x * blockDim.x + threadIdx.x;
    if (i < N_RELS * N_NODES) g_cnt[i] = 0;
    if (i < N_NODES) g_deg[i] = 0;
    if (i < 4) g_acc[i] = 0.0f;
}
__global__ void k_count(const int* __restrict__ ei, const int* __restrict__ et) {
    int e = blockIdx.x * blockDim.x + threadIdx.x;
    if (e >= N_EDGES) return;
    int d = ei[N_EDGES + e];
    atomicAdd(&g_cnt[et[e] * N_NODES + d], 1);
    atomicAdd(&g_deg[d], 1);
}
__global__ void k_scan() {
    __shared__ int part[1024];
    int tid = threadIdx.x;
    const int chunk = (N_NODES + 1023) / 1024;
    int lo = tid * chunk, hi = min(lo + chunk, N_NODES);
    int s = 0;
    for (int i = lo; i < hi; i++) s += g_deg[i];
    part[tid] = s;
    __syncthreads();
    for (int o = 1; o < 1024; o <<= 1) {
        int v = (tid >= o) ? part[tid - o] : 0;
        __syncthreads(); part[tid] += v; __syncthreads();
    }
    int run = part[tid] - s;
    for (int i = lo; i < hi; i++) { g_off[i] = run; g_cursor[i] = run; run += g_deg[i]; }
    if (tid == 1023) g_off[N_NODES] = run;
}
__global__ void k_scatter(const int* __restrict__ ei) {
    int e = blockIdx.x * blockDim.x + threadIdx.x;
    if (e >= N_EDGES) return;
    int p = atomicAdd(&g_cursor[ei[N_EDGES + e]], 1);
    g_esort[p] = e;
}
__global__ void k_wsplit(const float* __restrict__ Wroot, const float* __restrict__ Wr) {
    int idx = blockIdx.x * blockDim.x + threadIdx.x;
    if (idx >= N_LAYERS * GW * 256) return;
    int l = idx / (GW * 256), rem = idx % (GW * 256);
    int n = rem / 256, k = rem % 256;
    float v;
    if (n < 256) v = Wroot[((size_t)l * 256 + k) * 256 + n];
    else {
        int r = (n >> 8) - 1, h = n & 255;
        v = Wr[(((size_t)l * 4 + r) * 256 + k) * 256 + h];
    }
    __nv_bfloat16 hi = __float2bfloat16(v);
    g_Wh[idx] = hi;
    g_Wl[idx] = __float2bfloat16(v - __bfloat162float(hi));
}
__global__ void k_wsplitN(const float* __restrict__ nodeW) {
    int idx = blockIdx.x * blockDim.x + threadIdx.x;
    if (idx >= 256 * D_IN) return;
    int n = idx / D_IN, k = idx % D_IN;
    float v = nodeW[k * 256 + n];
    __nv_bfloat16 hi = __float2bfloat16(v);
    g_nWh[idx] = hi;
    g_nWl[idx] = __float2bfloat16(v - __bfloat162float(hi));
}
__global__ void k_asplit(const float* __restrict__ src, __nv_bfloat16* __restrict__ h,
                         __nv_bfloat16* __restrict__ l, int n) {
    int i = blockIdx.x * blockDim.x + threadIdx.x;
    if (i >= n) return;
    float v = src[i];
    __nv_bfloat16 hi = __float2bfloat16(v);
    h[i] = hi;
    l[i] = __float2bfloat16(v - __bfloat162float(hi));
}

// ---------------- pipelined bf16 tensor-core GEMM, BM=BN=128, BK=32, 2 stages ----------------
__device__ __forceinline__ void ldm4(uint32_t a, uint32_t& r0, uint32_t& r1,
                                     uint32_t& r2, uint32_t& r3) {
    asm volatile("ldmatrix.sync.aligned.m8n8.x4.shared.b16 {%0,%1,%2,%3}, [%4];"
                 : "=r"(r0), "=r"(r1), "=r"(r2), "=r"(r3) : "r"(a));
}
__device__ __forceinline__ void mma16816(float* c, const uint32_t* a, const uint32_t* b) {
    asm volatile("mma.sync.aligned.m16n8k16.row.col.f32.bf16.bf16.f32 "
                 "{%0,%1,%2,%3},{%4,%5,%6,%7},{%8,%9},{%0,%1,%2,%3};"
                 : "+f"(c[0]), "+f"(c[1]), "+f"(c[2]), "+f"(c[3])
                 : "r"(a[0]), "r"(a[1]), "r"(a[2]), "r"(a[3]), "r"(b[0]), "r"(b[1]));
}
__device__ __forceinline__ void cp16(uint32_t dst, const void* src) {
    asm volatile("cp.async.cg.shared.global [%0], [%1], 16;" :: "r"(dst), "l"(src));
}
// stage layout (elements): Ah 0, Al 5120, Bh 10240, Bl 15360; stage stride 20480 (40960 B)
#define LOAD_STAGE(s, kq)                                              \
    do {                                                               \
        uint32_t st_ = sm + (s) * 40960;                               \
        _Pragma("unroll")                                              \
        for (int q_ = 0; q_ < 2; q_++) {                               \
            int col_ = (c0 + q_) * 8;                                  \
            uint32_t dd_ = st_ + (row * 40 + col_) * 2;                \
            cp16(dd_,         Agh + (kq) + col_);                      \
            cp16(dd_ + 10240, Agl + (kq) + col_);                      \
            cp16(dd_ + 20480, Bgh + (kq) + col_);                      \
            cp16(dd_ + 30720, Bgl + (kq) + col_);                      \
        }                                                              \
    } while (0)

__global__ void __launch_bounds__(256, 1)
k_bmma(const __nv_bfloat16* __restrict__ Ah, const __nv_bfloat16* __restrict__ Al,
       const __nv_bfloat16* __restrict__ Bh, const __nv_bfloat16* __restrict__ Bl,
       const float* __restrict__ bias, float* __restrict__ C,
       int M, int N, int K, int relu_out) {
    extern __shared__ __align__(16) __nv_bfloat16 dsm[];
    uint32_t sm = (uint32_t)__cvta_generic_to_shared(dsm);
    int tid = threadIdx.x, lane = tid & 31, wid = tid >> 5;
    int wm = (wid >> 2) * 64, wn = (wid & 3) * 32;
    int bm = blockIdx.y * 128, bn = blockIdx.x * 128;
    int row = tid >> 1, c0 = (tid & 1) * 2;
    const __nv_bfloat16* Agh = Ah + (size_t)(bm + row) * K;
    const __nv_bfloat16* Agl = Al + (size_t)(bm + row) * K;
    const __nv_bfloat16* Bgh = Bh + (size_t)(bn + row) * K;
    const __nv_bfloat16* Bgl = Bl + (size_t)(bn + row) * K;

    float acc[4][4][4];
#pragma unroll
    for (int i = 0; i < 4; i++)
#pragma unroll
        for (int j = 0; j < 4; j++)
#pragma unroll
            for (int q = 0; q < 4; q++) acc[i][j][q] = 0.f;

    LOAD_STAGE(0, 0);
    asm volatile("cp.async.commit_group;");

    int cur = 0;
    for (int k0 = 0; k0 < K; k0 += 32) {
        int nxt = k0 + 32;
        if (nxt < K) LOAD_STAGE(cur ^ 1, nxt);
        asm volatile("cp.async.commit_group;");
        asm volatile("cp.async.wait_group 1;");
        __syncthreads();
        uint32_t st = sm + cur * 40960;
#pragma unroll
        for (int kk = 0; kk < 32; kk += 16) {
            uint32_t ah[4][4], al[4][4], bh[4][2], bl[4][2];
            int arow = wm + (lane & 7) + ((lane >> 3) & 1) * 8;
            int acol = kk + ((lane >> 4) & 1) * 8;
#pragma unroll
            for (int mf = 0; mf < 4; mf++) {
                uint32_t off = ((arow + mf * 16) * 40 + acol) * 2;
                ldm4(st + off, ah[mf][0], ah[mf][1], ah[mf][2], ah[mf][3]);
                ldm4(st + 10240 + off, al[mf][0], al[mf][1], al[mf][2], al[mf][3]);
            }
            int brow = wn + (lane & 7) + ((lane >> 4) & 1) * 8;
            int bcol = kk + ((lane >> 3) & 1) * 8;
#pragma unroll
            for (int nb = 0; nb < 2; nb++) {
                uint32_t off = ((brow + nb * 16) * 40 + bcol) * 2;
                ldm4(st + 20480 + off, bh[2 * nb][0], bh[2 * nb][1], bh[2 * nb + 1][0], bh[2 * nb + 1][1]);
                ldm4(st + 30720 + off, bl[2 * nb][0], bl[2 * nb][1], bl[2 * nb + 1][0], bl[2 * nb + 1][1]);
            }
#pragma unroll
            for (int mf = 0; mf < 4; mf++)
#pragma unroll
                for (int nf = 0; nf < 4; nf++) {
                    mma16816(acc[mf][nf], ah[mf], bh[nf]);
                    mma16816(acc[mf][nf], ah[mf], bl[nf]);
                    mma16816(acc[mf][nf], al[mf], bh[nf]);
                }
        }
        __syncthreads();
        cur ^= 1;
    }
#pragma unroll
    for (int mf = 0; mf < 4; mf++)
#pragma unroll
        for (int nf = 0; nf < 4; nf++) {
            int r0 = bm + wm + mf * 16 + (lane >> 2);
            int c0o = bn + wn + nf * 8 + (lane & 3) * 2;
#pragma unroll
            for (int h = 0; h < 2; h++) {
                int r = r0 + h * 8;
                if (r >= M) continue;
                float v0 = acc[mf][nf][2 * h], v1 = acc[mf][nf][2 * h + 1];
                if (bias) { v0 += bias[c0o]; v1 += bias[c0o + 1]; }
                if (relu_out) { v0 = fmaxf(v0, 0.f); v1 = fmaxf(v1, 0.f); }
                *(float2*)(C + (size_t)r * N + c0o) = make_float2(v0, v1);
            }
        }
}

__global__ void __launch_bounds__(256)
k_sgemm(const float* __restrict__ A, const float* __restrict__ B,
        const float* __restrict__ bias, float* __restrict__ C,
        int M, int N, int K, int relu_in, int relu_out) {
    __shared__ float As[8][128];
    __shared__ float Bs[8][128];
    int bm = blockIdx.y * 128, bn = blockIdx.x * 128;
    int tid = threadIdx.x, tr = tid >> 4, tc = tid & 15;
    float acc[8][8];
#pragma unroll
    for (int i = 0; i < 8; i++)
#pragma unroll
        for (int j = 0; j < 8; j++) acc[i][j] = 0.f;
    int aRow = tid >> 1, aCol = (tid & 1) * 4;
    int bRow = tid >> 5, bCol = (tid & 31) * 4;
    for (int k0 = 0; k0 < K; k0 += 8) {
        float4 av = make_float4(0.f, 0.f, 0.f, 0.f);
        if (bm + aRow < M)
            av = *(const float4*)(A + (size_t)(bm + aRow) * K + k0 + aCol);
        if (relu_in) {
            av.x = fmaxf(av.x, 0.f); av.y = fmaxf(av.y, 0.f);
            av.z = fmaxf(av.z, 0.f); av.w = fmaxf(av.w, 0.f);
        }
        As[aCol + 0][aRow] = av.x; As[aCol + 1][aRow] = av.y;
        As[aCol + 2][aRow] = av.z; As[aCol + 3][aRow] = av.w;
        float4 bv = make_float4(0.f, 0.f, 0.f, 0.f);
        if (bn + bCol < N)
            bv = *(const float4*)(B + (size_t)(k0 + bRow) * N + bn + bCol);
        *(float4*)&Bs[bRow][bCol] = bv;
        __syncthreads();
#pragma unroll
        for (int kk = 0; kk < 8; kk++) {
            float a[8], b[8];
            *(float4*)(a)     = *(const float4*)&As[kk][tr * 8];
            *(float4*)(a + 4) = *(const float4*)&As[kk][tr * 8 + 4];
            *(float4*)(b)     = *(const float4*)&Bs[kk][tc * 8];
            *(float4*)(b + 4) = *(const float4*)&Bs[kk][tc * 8 + 4];
#pragma unroll
            for (int i = 0; i < 8; i++)
#pragma unroll
                for (int j = 0; j < 8; j++) acc[i][j] = fmaf(a[i], b[j], acc[i][j]);
        }
        __syncthreads();
    }
#pragma unroll
    for (int i = 0; i < 8; i++) {
        int row = bm + tr * 8 + i;
        if (row >= M) continue;
#pragma unroll
        for (int j = 0; j < 8; j++) {
            int col = bn + tc * 8 + j;
            if (col >= N) continue;
            float v = acc[i][j];
            if (bias) v += bias[col];
            if (relu_out) v = fmaxf(v, 0.f);
            C[(size_t)row * N + col] = v;
        }
    }
}

// aggregation; for hidden layers writes relu'd result split to bf16 hi/lo,
// for the last layer writes fp32
__global__ void k_agg(const int* __restrict__ ei, const int* __restrict__ et,
                      const float* __restrict__ bias,
                      __nv_bfloat16* __restrict__ oh, __nv_bfloat16* __restrict__ ol,
                      float* __restrict__ out32, int relu) {
    int d = (blockIdx.x * blockDim.x + threadIdx.x) >> 5;
    int lane = threadIdx.x & 31;
    if (d >= N_NODES) return;
    float acc[8];
    const float* g0 = g_G + (size_t)d * GW;
#pragma unroll
    for (int j = 0; j < 8; j++) acc[j] = g0[lane + 32 * j] + bias[lane + 32 * j];
    int s = g_off[d], e = g_off[d + 1];
    for (int i = s; i < e; i++) {
        int eid = g_esort[i];
        int sn = ei[eid], r = et[eid];
        float inv = 1.0f / (float)g_cnt[r * N_NODES + d];
        const float* gp = g_G + (size_t)sn * GW + 256 + (r << 8);
#pragma unroll
        for (int j = 0; j < 8; j++) acc[j] = fmaf(gp[lane + 32 * j], inv, acc[j]);
    }
    if (relu) {
#pragma unroll
        for (int j = 0; j < 8; j++) {
            float v = fmaxf(acc[j], 0.f);
            __nv_bfloat16 hi = __float2bfloat16(v);
            size_t idx = (size_t)d * DD + lane + 32 * j;
            oh[idx] = hi;
            ol[idx] = __float2bfloat16(v - __bfloat162float(hi));
        }
    } else {
#pragma unroll
        for (int j = 0; j < 8; j++)
            out32[(size_t)d * DD + lane + 32 * j] = acc[j];
    }
}

__global__ void k_starts(const int* __restrict__ batch) {
    int m = blockIdx.x * blockDim.x + threadIdx.x;
    if (m > NUM_M) return;
    int lo = 0, hi = N_NODES;
    while (lo < hi) { int mid = (lo + hi) >> 1; if (batch[mid] < m) lo = mid + 1; else hi = mid; }
    g_start[m] = lo;
}
__global__ void k_copyHR(const float* __restrict__ HR) {
    int i = blockIdx.x * blockDim.x + threadIdx.x;
    if (i < NUM_R * DD) g_Hall[i] = HR[i];
}
__global__ void k_gmean(const float* __restrict__ feats) {
    int m = blockIdx.x, c = threadIdx.x;
    int s = g_start[m], e = g_start[m + 1];
    float acc = 0.f;
    for (int n = s; n < e; n++) acc += feats[(size_t)n * DD + c];
    g_Hall[(size_t)(NUM_R + m) * DD + c] = acc / fmaxf((float)(e - s), 1.0f);
}

__global__ void k_sample_u(unsigned k0, unsigned k1) {
    int i = blockIdx.x * blockDim.x + threadIdx.x;
    if (i >= N_ALL * DD) return;
    int row = i >> 8, col = i & 255;
    g_u[i] = g_pu[row * 512 + col] + expf(g_pu[row * 512 + 256 + col]) * nrm(rbits(k0, k1, i));
}
__global__ void k_sample_zM(unsigned k0, unsigned k1) {
    int i = blockIdx.x * blockDim.x + threadIdx.x;
    if (i >= NUM_M * DD) return;
    int m = i >> 8, col = i & 255;
    int r = (NUM_R + m) * 512;
    g_zM[i] = g_qz[r + col] + expf(g_qz[r + 256 + col]) * nrm(rbits(k0, k1, i));
}
__global__ void k_sample_zR(unsigned k0, unsigned k1) {
    int i = blockIdx.x * blockDim.x + threadIdx.x;
    if (i >= NUM_R * DD) return;
    int r = i >> 8, col = i & 255;
    g_zR[i] = g_qz[r * 512 + col] + expf(g_qz[r * 512 + 256 + col]) * nrm(rbits(k0, k1, i));
}

__global__ void k_attn(const float* __restrict__ pg, const int* __restrict__ yM,
                       unsigned k0, unsigned k1) {
    int m = blockIdx.x, r = threadIdx.x;
    __shared__ float um[DD];
    __shared__ float d2s[NUM_R];
    __shared__ float red[NUM_R];
    for (int i = r; i < DD; i += 64) um[i] = g_u[(size_t)(NUM_R + m) * DD + i];
    __syncthreads();
    float d2 = 0.f;
    const float* ur = g_u + (size_t)r * DD;
    for (int dd = 0; dd < DD; dd++) {
        float t = um[dd] - ur[dd];
        d2 = fmaf(t, t, d2);
    }
    d2s[r] = d2;
    float logp = -0.5f * d2 / expf(pg[0]);
    float logit = logp - logf(fmaxf(-expm1f(logp), 1e-20f));
    float U = unif(rbits(k0, k1, (uint32_t)(m * NUM_R + r)));
    float gn = logf(U) - log1pf(-U);
    float A = 1.0f / (1.0f + expf(-(logit + gn) / 0.3f));
    red[r] = A;
    __syncthreads();
    for (int o = 32; o >= 1; o >>= 1) {
        if (r < o) red[r] += red[r + o];
        __syncthreads();
    }
    g_An[m * NUM_R + r] = A / (red[0] + 1e-8f);
    if (r < 32) {
        int idx = r + (1 - yM[m]) * 32;
        float t = sqrtf(fmaxf(d2s[idx], 1e-12f));
        for (int o = 16; o >= 1; o >>= 1) t += __shfl_down_sync(0xffffffffu, t, o);
        if (r == 0) atomicAdd(&g_acc[3], t);
    }
}

__global__ void k_pz() {
    int m = blockIdx.x, c = threadIdx.x;
    __shared__ float an[NUM_R];
    if (c < NUM_R) an[c] = g_An[m * NUM_R + c];
    __syncthreads();
    float s0 = 0.f, s1 = 0.f;
    for (int r = 0; r < NUM_R; r++) {
        float a = an[r];
        s0 = fmaf(a, g_qz[r * 512 + c], s0);
        s1 = fmaf(a, g_qz[r * 512 + 256 + c], s1);
    }
    g_pzm[m * DD + c] = s0;
    g_pzl[m * DD + c] = s1;
}

__global__ void k_pqz() {
    int m = blockIdx.x, c = threadIdx.x;
    float z = g_zM[m * DD + c];
    float pm = g_pzm[m * DD + c], pl = g_pzl[m * DD + c];
    float qm = g_qz[(NUM_R + m) * 512 + c], ql = g_qz[(NUM_R + m) * 512 + 256 + c];
    float t1 = (z - pm) * expf(-pl);
    float t2 = (z - qm) * expf(-ql);
    float v = (-pl - 0.5f * t1 * t1) - (-ql - 0.5f * t2 * t2);
    __shared__ float red[256];
    red[c] = v;
    __syncthreads();
    for (int o = 128; o >= 1; o >>= 1) {
        if (c < o) red[c] += red[c + o];
        __syncthreads();
    }
    if (c == 0) atomicAdd(&g_acc[1], red[0]);
}

__global__ void k_repM() {
    int i = blockIdx.x * blockDim.x + threadIdx.x;
    if (i >= NUM_M * 512) return;
    int m = i >> 9, c = i & 511;
    g_repM[i] = (c < 256) ? g_zM[m * DD + c] : g_u[(size_t)(NUM_R + m) * DD + (c - 256)];
}
__global__ void k_repR() {
    int i = blockIdx.x * blockDim.x + threadIdx.x;
    if (i >= NUM_R * 512) return;
    int r = i >> 9, c = i & 511;
    g_repR[i] = (c < 256) ? g_zR[r * DD + c] : g_u[(size_t)r * DD + (c - 256)];
}

__global__ void k_head(const float* __restrict__ hid, const float* __restrict__ W2,
                       const float* __restrict__ b2, const int* __restrict__ y,
                       int rows, int accIdx) {
    int gw = (blockIdx.x * blockDim.x + threadIdx.x) >> 5;
    int lane = threadIdx.x & 31;
    if (gw >= rows) return;
    float p0 = 0.f, p1 = 0.f;
#pragma unroll
    for (int j = 0; j < 8; j++) {
        int k = lane + 32 * j;
        float h = hid[(size_t)gw * 256 + k];
        p0 = fmaf(h, W2[k * 2], p0);
        p1 = fmaf(h, W2[k * 2 + 1], p1);
    }
    for (int o = 16; o >= 1; o >>= 1) {
        p0 += __shfl_down_sync(0xffffffffu, p0, o);
        p1 += __shfl_down_sync(0xffffffffu, p1, o);
    }
    if (lane == 0) {
        float l0 = p0 + b2[0], l1 = p1 + b2[1];
        float mx = fmaxf(l0, l1);
        float lse = mx + logf(expf(l0 - mx) + expf(l1 - mx));
        atomicAdd(&g_acc[accIdx], ((y[gw] != 0) ? l1 : l0) - lse);
    }
}

__global__ void k_final(float* __restrict__ out) {
    float pred = -(g_acc[0] + 0.1f * g_acc[1]) / 1024.0f;
    float rat  = -g_acc[2] / 64.0f;
    float reg  = g_acc[3] / 32768.0f;
    out[0] = pred + rat - 0.1f * reg;
}

extern "C" void kernel_launch(void* const* d_in, const int* in_sizes, int n_in,
                              void* d_out, int out_size) {
    (void)in_sizes; (void)n_in; (void)out_size;
    const float* x     = (const float*)d_in[0];
    const int*   ei    = (const int*)  d_in[1];
    const int*   et    = (const int*)  d_in[2];
    const int*   batch = (const int*)  d_in[3];
    const int*   yM    = (const int*)  d_in[4];
    const int*   yR    = (const int*)  d_in[5];
    const float* HR    = (const float*)d_in[6];
    const float* nodeW = (const float*)d_in[7];
    const float* nodeB = (const float*)d_in[8];
    const float* Wr    = (const float*)d_in[9];
    const float* Wroot = (const float*)d_in[10];
    const float* gcnB  = (const float*)d_in[11];
    const float* pg    = (const float*)d_in[12];
    const float* puW   = (const float*)d_in[13];
    const float* puB   = (const float*)d_in[14];
    const float* qzW   = (const float*)d_in[15];
    const float* qzB   = (const float*)d_in[16];
    const float* W1    = (const float*)d_in[17];
    const float* b1    = (const float*)d_in[18];
    const float* W2    = (const float*)d_in[19];
    const float* b2    = (const float*)d_in[20];
    float* out = (float*)d_out;

    uint32_t ku0, ku1, ka0, ka1, kzm0, kzm1, kzr0, kzr1;
    tf2x32(0u, 42u, 0u, 0u, ku0, ku1);
    tf2x32(0u, 42u, 0u, 1u, ka0, ka1);
    tf2x32(0u, 42u, 0u, 2u, kzm0, kzm1);
    tf2x32(0u, 42u, 0u, 3u, kzr0, kzr1);

    void* p;
    cudaGetSymbolAddress(&p, g_featsA); float* featsA = (float*)p;
    cudaGetSymbolAddress(&p, g_featsB); float* featsB = (float*)p;
    cudaGetSymbolAddress(&p, g_G);      float* G      = (float*)p;
    cudaGetSymbolAddress(&p, g_Wh);     __nv_bfloat16* Wh  = (__nv_bfloat16*)p;
    cudaGetSymbolAddress(&p, g_Wl);     __nv_bfloat16* Wl  = (__nv_bfloat16*)p;
    cudaGetSymbolAddress(&p, g_nWh);    __nv_bfloat16* nWh = (__nv_bfloat16*)p;
    cudaGetSymbolAddress(&p, g_nWl);    __nv_bfloat16* nWl = (__nv_bfloat16*)p;
    cudaGetSymbolAddress(&p, g_xh);     __nv_bfloat16* xh  = (__nv_bfloat16*)p;
    cudaGetSymbolAddress(&p, g_xl);     __nv_bfloat16* xl  = (__nv_bfloat16*)p;
    cudaGetSymbolAddress(&p, g_Ah);     __nv_bfloat16* Ahp = (__nv_bfloat16*)p;
    cudaGetSymbolAddress(&p, g_Al);     __nv_bfloat16* Alp = (__nv_bfloat16*)p;
    cudaGetSymbolAddress(&p, g_Hall);   float* Hall   = (float*)p;
    cudaGetSymbolAddress(&p, g_pu);     float* pu     = (float*)p;
    cudaGetSymbolAddress(&p, g_qz);     float* qz     = (float*)p;
    cudaGetSymbolAddress(&p, g_repM);   float* repM   = (float*)p;
    cudaGetSymbolAddress(&p, g_repR);   float* repR   = (float*)p;
    cudaGetSymbolAddress(&p, g_hidM);   float* hidM   = (float*)p;
    cudaGetSymbolAddress(&p, g_hidR);   float* hidR   = (float*)p;

    static int smem_set = 0;
    if (!smem_set) {
        cudaFuncSetAttribute(k_bmma, cudaFuncAttributeMaxDynamicSharedMemorySize, 81920);
        smem_set = 1;
    }

    k_zero_init<<<(N_RELS * N_NODES + 255) / 256, 256>>>();
    k_count<<<(N_EDGES + 255) / 256, 256>>>(ei, et);
    k_scan<<<1, 1024>>>();
    k_scatter<<<(N_EDGES + 255) / 256, 256>>>(ei);
    k_wsplit<<<(N_LAYERS * GW * 256 + 255) / 256, 256>>>(Wroot, Wr);
    k_wsplitN<<<(256 * D_IN + 255) / 256, 256>>>(nodeW);
    k_asplit<<<(N_NODES * D_IN + 255) / 256, 256>>>(x, xh, xl, N_NODES * D_IN);

    // node encoder on tensor cores
    k_bmma<<<dim3(2, (N_NODES + 127) / 128), 256, 81920>>>(
        xh, xl, nWh, nWl, nodeB, featsA, N_NODES, 256, D_IN, 0);
    k_asplit<<<(N_NODES * DD + 255) / 256, 256>>>(featsA, Ahp, Alp, N_NODES * DD);

    for (int l = 0; l < N_LAYERS; l++) {
        k_bmma<<<dim3(GW / 128, (N_NODES + 127) / 128), 256, 81920>>>(
            Ahp, Alp, Wh + (size_t)l * GW * 256, Wl + (size_t)l * GW * 256,
            nullptr, G, N_NODES, GW, 256, 0);
        k_agg<<<(N_NODES * 32 + 255) / 256, 256>>>(
            ei, et, gcnB + l * 256, Ahp, Alp, featsB, (l < N_LAYERS - 1) ? 1 : 0);
    }

    k_starts<<<(NUM_M + 256) / 256, 256>>>(batch);
    k_copyHR<<<(NUM_R * DD + 255) / 256, 256>>>(HR);
    k_gmean<<<NUM_M, 256>>>(featsB);

    k_sgemm<<<dim3(4, (N_ALL + 127) / 128), 256>>>(Hall, puW, puB, pu, N_ALL, 512, 256, 1, 0);
    k_sgemm<<<dim3(4, (N_ALL + 127) / 128), 256>>>(Hall, qzW, qzB, qz, N_ALL, 512, 256, 1, 0);

    k_sample_u <<<(N_ALL * DD + 255) / 256, 256>>>(ku0, ku1);
    k_sample_zM<<<(NUM_M * DD + 255) / 256, 256>>>(kzm0, kzm1);
    k_sample_zR<<<(NUM_R * DD + 255) / 256, 256>>>(kzr0, kzr1);

    k_attn<<<NUM_M, 64>>>(pg, yM, ka0, ka1);
    k_pz  <<<NUM_M, 256>>>();
    k_pqz <<<NUM_M, 256>>>();

    k_repM<<<(NUM_M * 512 + 255) / 256, 256>>>();
    k_repR<<<(NUM_R * 512 + 255) / 256, 256>>>();
    k_sgemm<<<dim3(2, (NUM_M + 127) / 128), 256>>>(repM, W1, b1, hidM, NUM_M, 256, 512, 0, 1);
    k_sgemm<<<dim3(2, 1), 256>>>(repR, W1, b1, hidR, NUM_R, 256, 512, 0, 1);
    k_head<<<(NUM_M * 32 + 255) / 256, 256>>>(hidM, W2, b2, yM, NUM_M, 0);
    k_head<<<(NUM_R * 32 + 255) / 256, 256>>>(hidR, W2, b2, yR, NUM_R, 2);

    k_final<<<1, 1>>>(out);
}